// round 4
// baseline (speedup 1.0000x reference)
#include <cuda_runtime.h>

// Shift_14422500180434: 3x3 spatial shift "im2col-lite".
//   x:   [32, 64, 56, 56] f32 -> out: [32, 576, 56, 56] f32
//   out[n, c*9 + 3*dy + dx, h, w] = x[n, c, h+dy-1, w+dx-1] (zero pad)
//
// R3 (resubmit after infra flake): one block per (n,c). Input plane (12.5KB)
// staged once in padded smem (58x60, zero borders). Each block then writes its
// 113KB output region (9 contiguous planes) with long sequential __stcs
// bursts. Each output triple (dx=0,1,2) comes from two aligned LDS.128 +
// register selects.

#define PLANE_ 3136           // 56*56
#define SROW_ 60              // padded smem row stride (floats), 16B-aligned
#define NPLANES_ 2048         // 32*64 (n,c) pairs

__global__ __launch_bounds__(256) void shift_kernel(
    const float* __restrict__ x, float* __restrict__ out)
{
    __shared__ __align__(16) float sp[58 * SROW_];  // sp[r][c] = x(r-1, c-1), 0 outside
    const int tid = threadIdx.x;
    const int b = blockIdx.x;          // n*64 + c

    // Zero the whole padded plane (870 float4).
    const float4 z = make_float4(0.f, 0.f, 0.f, 0.f);
    for (int i = tid; i < (58 * SROW_) / 4; i += 256)
        reinterpret_cast<float4*>(sp)[i] = z;
    __syncthreads();

    // Load input plane: 784 float4, scatter as scalars into the padded frame.
    const float* __restrict__ xp = x + (long)b * PLANE_;
    for (int i = tid; i < PLANE_ / 4; i += 256) {
        float4 v = reinterpret_cast<const float4*>(xp)[i];
        int r = i / 14, c4 = i % 14;
        float* d = sp + (r + 1) * SROW_ + (4 * c4 + 1);
        d[0] = v.x; d[1] = v.y; d[2] = v.z; d[3] = v.w;
    }
    __syncthreads();

    // Write 9 shifted planes, contiguous within this block's 113KB region.
    float* __restrict__ ob = out + (long)b * 9 * PLANE_;
#pragma unroll
    for (int dy = 0; dy < 3; ++dy) {
        for (int p = tid; p < PLANE_ / 4; p += 256) {
            int h = p / 14, w0 = (p % 14) * 4;
            const float* rp = sp + (h + dy) * SROW_ + w0;   // 16B-aligned
            float4 A = *reinterpret_cast<const float4*>(rp);
            float4 B = *reinterpret_cast<const float4*>(rp + 4);
            float* o = ob + (long)(dy * 3) * PLANE_ + p * 4;
            __stcs(reinterpret_cast<float4*>(o), A);                       // dx=0
            __stcs(reinterpret_cast<float4*>(o + PLANE_),
                   make_float4(A.y, A.z, A.w, B.x));                       // dx=1
            __stcs(reinterpret_cast<float4*>(o + 2 * PLANE_),
                   make_float4(A.z, A.w, B.x, B.y));                       // dx=2
        }
    }
}

extern "C" void kernel_launch(void* const* d_in, const int* in_sizes, int n_in,
                              void* d_out, int out_size)
{
    const float* x = (const float*)d_in[0];
    float* out = (float*)d_out;
    shift_kernel<<<NPLANES_, 256>>>(x, out);
}

// round 5
// speedup vs baseline: 1.0524x; 1.0524x over previous
#include <cuda_runtime.h>

// Shift_14422500180434: 3x3 spatial shift "im2col-lite".
//   x:   [32, 64, 56, 56] f32 -> out: [32, 576, 56, 56] f32
//   out[n, c*9 + 3*dy + dx, h, w] = x[n, c, h+dy-1, w+dx-1] (zero pad)
//
// R5: back to the R2 direct design (best: 39.0us), plus h-pairing.
// One thread = (n, c, h-pair, w4). Loads 4 overlapping input rows
// (12 LDG instead of 18), emits 18 independent STG.128 (__stcs).
// Exact grid, no bounds guard.

#define N_ 32
#define C_ 64
#define H_ 56
#define W_ 56
#define W4_ 14              // W/4
#define H2_ 28              // H/2
#define PLANE_ (H_ * W_)    // 3136
#define TOTAL_THREADS_ (N_ * C_ * H2_ * W4_)   // 802,816 = 3136 * 256

__global__ __launch_bounds__(256) void shift_kernel(
    const float* __restrict__ x, float* __restrict__ out)
{
    int t = blockIdx.x * blockDim.x + threadIdx.x;

    int w4 = t % W4_;
    int h2 = (t / W4_) % H2_;
    int c  = (t / (W4_ * H2_)) % C_;
    int n  = t / (W4_ * H2_ * C_);
    int h  = h2 * 2;
    int w0 = w4 * 4;

    const float* __restrict__ xp = x + ((n * C_ + c) * H_) * (long)W_ + w0;

    // rows[r][j]: input float at (h - 1 + r, w0 + j - 1), j = 0..5, 0 outside.
    float rows[4][6];
#pragma unroll
    for (int r = 0; r < 4; ++r) {
        int hh = h - 1 + r;
        bool hv = ((unsigned)hh < (unsigned)H_);
        float4 v = make_float4(0.f, 0.f, 0.f, 0.f);
        float left = 0.f, right = 0.f;
        if (hv) {
            const float* rp = xp + hh * W_;
            v = *reinterpret_cast<const float4*>(rp);
            if (w4 > 0)       left  = rp[-1];
            if (w4 < W4_ - 1) right = rp[4];
        }
        rows[r][0] = left;
        rows[r][1] = v.x; rows[r][2] = v.y; rows[r][3] = v.z; rows[r][4] = v.w;
        rows[r][5] = right;
    }

    // Output base for shift s=0 at (n, c, h, w0); planes PLANE_ apart.
    float* __restrict__ op =
        out + (((long)(n * (C_ * 9) + c * 9)) * H_ + h) * W_ + w0;

#pragma unroll
    for (int oh = 0; oh < 2; ++oh) {
#pragma unroll
        for (int dy = 0; dy < 3; ++dy) {
            const float* r = rows[oh + dy];
            float* o = op + oh * W_ + (long)(dy * 3) * PLANE_;
            __stcs(reinterpret_cast<float4*>(o),
                   make_float4(r[0], r[1], r[2], r[3]));           // dx=0
            __stcs(reinterpret_cast<float4*>(o + PLANE_),
                   make_float4(r[1], r[2], r[3], r[4]));           // dx=1
            __stcs(reinterpret_cast<float4*>(o + 2 * PLANE_),
                   make_float4(r[2], r[3], r[4], r[5]));           // dx=2
        }
    }
}

extern "C" void kernel_launch(void* const* d_in, const int* in_sizes, int n_in,
                              void* d_out, int out_size)
{
    const float* x = (const float*)d_in[0];
    float* out = (float*)d_out;
    const int threads = 256;
    const int blocks = TOTAL_THREADS_ / threads;  // 3136, exact
    shift_kernel<<<blocks, threads>>>(x, out);
}